// round 15
// baseline (speedup 1.0000x reference)
#include <cuda_runtime.h>
#include <cuda_fp16.h>
#include <cstdint>

// NF4 quantized linear via single-term fp16 mma.sync (sm_103, non-'a' target).
// out[m][n] = sum_k x[m][k] * LUT[nib(packed[n][k])] * absmax[n] + bias[n]
// M=8192, N=4096, K=4096.
//
// R14: X fp32->fp16 conversion fused into the GEMM producer (build_x deleted,
// saving its 192 MB DRAM round-trip). 256 threads, BK=128, warptile 64x64,
// 2-stage: W via cp.async from the pre-built fp16 image, X via coalesced
// LDG.128 fp32 -> cvt -> swizzled STS.64 one chunk ahead. ldmatrix/MMA side
// identical to R13 (256B smem rows, per-half XOR swizzle).

#define M_DIM 8192
#define N_DIM 4096
#define K_DIM 4096
#define KC64  (K_DIM / 64)        // 64 k64-blocks per W-image row
#define KH    (K_DIM / 2)         // packed byte count per W row

#define BM 128
#define BN 256
#define NCHUNK 32                 // K-chunks of 128
#define NTH 256
#define STAGES 2
#define XS_BYTES 32768            // 128 rows x 256B fp16
#define WS_BYTES 65536            // 256 rows x 256B fp16
#define STAGE_BYTES (XS_BYTES + WS_BYTES)       // 98304
#define SMEM_DYN (STAGES * STAGE_BYTES)         // 196608

__device__ uint8_t g_wh[(size_t)N_DIM * KC64 * 128];   // 32 MB fp16 W image

__constant__ float NF4_TAB[16] = {
    -1.0f, -0.6961928009986877f, -0.5250730514526367f, -0.39491748809814453f,
    -0.28444138169288635f, -0.18477343022823334f, -0.09105003625154495f, 0.0f,
    0.07958029955625534f, 0.16093020141124725f, 0.24611230194568634f,
    0.33791524171829224f, 0.44070982933044434f, 0.5626170039176941f,
    0.7229568362236023f, 1.0f};

// ---------------- PTX helpers (arch-agnostic, sm_80+) ----------------
#define CP_ASYNC16(smem_u32, gptr)                                             \
    asm volatile("cp.async.cg.shared.global [%0], [%1], 16;"                   \
                 :: "r"(smem_u32), "l"(gptr))
#define CP_COMMIT() asm volatile("cp.async.commit_group;" ::: "memory")
#define CP_WAIT(n)  asm volatile("cp.async.wait_group %0;" :: "n"(n) : "memory")

#define LDSM4(r0, r1, r2, r3, addr)                                            \
    asm volatile("ldmatrix.sync.aligned.m8n8.x4.shared.b16 {%0,%1,%2,%3}, [%4];" \
                 : "=r"(r0), "=r"(r1), "=r"(r2), "=r"(r3) : "r"(addr))

#define MMA16816(d, a, b0, b1)                                                 \
    asm volatile("mma.sync.aligned.m16n8k16.row.col.f32.f16.f16.f32 "          \
                 "{%0,%1,%2,%3}, {%4,%5,%6,%7}, {%8,%9}, {%0,%1,%2,%3};"       \
                 : "+f"((d)[0]), "+f"((d)[1]), "+f"((d)[2]), "+f"((d)[3])      \
                 : "r"((a)[0]), "r"((a)[1]), "r"((a)[2]), "r"((a)[3]),         \
                   "r"(b0), "r"(b1))

#define STS64(addr, r0, r1)                                                    \
    asm volatile("st.shared.v2.u32 [%0], {%1, %2};"                            \
                 :: "r"(addr), "r"(r0), "r"(r1) : "memory")

// pack (fp16(a), fp16(b)) -> u32 {b<<16 | a}
__device__ __forceinline__ uint32_t pack_f16x2(float a, float b) {
    uint32_t r;
    asm("cvt.rn.f16x2.f32 %0, %1, %2;" : "=r"(r) : "f"(b), "f"(a));
    return r;
}

// ---------------- pre-pass: NF4 dequant -> fp16, swizzled (coalesced) ------
__global__ __launch_bounds__(256)
void build_w_kernel(const int* __restrict__ packed) {
    __shared__ uint16_t lut[16];   // fp16 bits of NF4 level
    if (threadIdx.x < 16)
        lut[threadIdx.x] = (uint16_t)(pack_f16x2(NF4_TAB[threadIdx.x], 0.0f) & 0xFFFFu);
    __syncthreads();

    const size_t gt = (size_t)blockIdx.x * 256 + threadIdx.x;
    const size_t id = gt >> 3;                 // block index: n*KC64 + kc
    const int    j  = (int)(gt & 7);
    const int kc = (int)(id & (KC64 - 1));
    const int n  = (int)(id >> 6);

    const int4 pv = reinterpret_cast<const int4*>(packed)
                        [(size_t)n * (KH / 4) + kc * 8 + j];
    const uint32_t byts[4] = {(uint32_t)pv.x & 255u, (uint32_t)pv.y & 255u,
                              (uint32_t)pv.z & 255u, (uint32_t)pv.w & 255u};
    uint32_t w[4];
#pragma unroll
    for (int e = 0; e < 4; e++) {
        const uint32_t b = byts[e];
        // k even = high nibble, k odd = low nibble
        w[e] = (uint32_t)lut[b >> 4] | ((uint32_t)lut[b & 15u] << 16);
    }
    *reinterpret_cast<uint4*>(g_wh + id * 128 + ((j ^ (n & 7)) * 16)) =
        make_uint4(w[0], w[1], w[2], w[3]);
}

// ---------------- main GEMM: fused X convert + cp.async W + HMMA ----------
__global__ __launch_bounds__(NTH, 1)
void nf4_hmma_kernel(const float* __restrict__ x,
                     const float* __restrict__ absmax,
                     const float* __restrict__ bias,
                     float* __restrict__ out) {
    extern __shared__ __align__(1024) uint8_t smem[];
    const uint32_t sbase = (uint32_t)__cvta_generic_to_shared(smem);

    const int tid  = threadIdx.x;
    const int wid  = tid >> 5;
    const int lane = tid & 31;
    const int bm = blockIdx.y * BM;
    const int bn = blockIdx.x * BN;
    const int wm = (wid & 1) * 64;     // 2 warps in m, warptile m=64
    const int wn = (wid >> 1) * 64;    // 4 warps in n, warptile n=64

    // ---- per-lane ldmatrix address components (verified R8-R13) ----
    const int s7 = lane & 7;
    const int rl = s7 + 8 * ((lane >> 3) & 1);       // A row-in-16
    const int pa = lane >> 4;                        // A k-half bit
    const int nl = s7 + 8 * (lane >> 4);             // B n-in-16
    const int kb = (lane >> 3) & 1;                  // B k-half bit
    const uint32_t xlb = (uint32_t)(wm + rl) * 256;  // 256B rows
    const uint32_t wlb = (uint32_t)(wn + nl) * 256;

    uint32_t a_sw[8], b_sw[8];   // per k16-step offsets within the 256B row
#pragma unroll
    for (int ks = 0; ks < 8; ks++) {
        const int half = ks >> 2, k4 = ks & 3;
        a_sw[ks] = (uint32_t)(half * 128 + ((2 * k4 + pa) ^ s7) * 16);
        b_sw[ks] = (uint32_t)(half * 128 + ((2 * k4 + kb) ^ s7) * 16);
    }

    // ---- X producer mapping: q = tid + i*256 -> row=q>>5, f4=q&31 ----
    // (one full 512B row per warp per LDG.128 -> fully coalesced)
    const int xrow0 = tid >> 5;          // rows xrow0 + 8i
    const int xf4   = tid & 31;          // float4 index in row (k = 4*f4)
    const int xhalf = xf4 >> 4;          // k-half within 256B smem row
    const uint32_t xsts_base =
        (uint32_t)(xhalf * 128 + (((xf4 >> 1) & 7) /*j*/ * 0) );  // per-i below
    (void)xsts_base;

    float4   xa[8];    // fp32 staging (one half-chunk)
    uint32_t xc[32];   // fp16x2 staging for next chunk (16 f4 * 2)

    auto ldg_half = [&](int c, int h) {
#pragma unroll
        for (int ii = 0; ii < 8; ii++) {
            const int row = xrow0 + 8 * (h * 8 + ii);
            xa[ii] = *reinterpret_cast<const float4*>(
                x + (size_t)(bm + row) * K_DIM + c * 128 + xf4 * 4);
        }
    };
    auto cvt_half = [&](int h) {
#pragma unroll
        for (int ii = 0; ii < 8; ii++) {
            xc[(h * 8 + ii) * 2 + 0] = pack_f16x2(xa[ii].x, xa[ii].y);
            xc[(h * 8 + ii) * 2 + 1] = pack_f16x2(xa[ii].z, xa[ii].w);
        }
    };
    auto sts_x = [&](int c) {   // store xc into X stage (c&1)
        const uint32_t xb = sbase + (uint32_t)(c & 1) * STAGE_BYTES;
        const int j = (xf4 >> 1) & 7, o8 = xf4 & 1;
#pragma unroll
        for (int i = 0; i < 16; i++) {
            const int row = xrow0 + 8 * i;
            const uint32_t addr = xb + (uint32_t)row * 256 + xhalf * 128 +
                                  (uint32_t)(((j ^ (row & 7)) * 16) + o8 * 8);
            STS64(addr, xc[2 * i], xc[2 * i + 1]);
        }
    };

    // ---- W producer: identity cp.async from image, 16 x 16B per thread ----
    auto issue_w = [&](int c) {
        const uint32_t sb = sbase + (uint32_t)(c & 1) * STAGE_BYTES + XS_BYTES;
#pragma unroll
        for (int i = 0; i < 16; i++) {
            const int q = tid + i * NTH;
            const int row = q >> 4, sub = q & 15;
            const int half = sub >> 3, j = sub & 7;
            const uint8_t* gw =
                g_wh + (((size_t)(bn + row)) * KC64 + 2 * c + half) * 128 + j * 16;
            CP_ASYNC16(sb + row * 256 + half * 128 + j * 16, gw);
        }
    };

    float acc[4][8][4];
#pragma unroll
    for (int mt = 0; mt < 4; mt++)
#pragma unroll
        for (int nt = 0; nt < 8; nt++)
#pragma unroll
            for (int e = 0; e < 4; e++) acc[mt][nt][e] = 0.0f;

    // ---- prologue ----
    ldg_half(0, 0); cvt_half(0); ldg_half(0, 1); cvt_half(1);
    sts_x(0);                                   // X stage 0 = chunk 0
    ldg_half(1, 0); cvt_half(0); ldg_half(1, 1); cvt_half(1);  // xc = chunk 1
    issue_w(0); CP_COMMIT();
    issue_w(1); CP_COMMIT();

    // ---- mainloop ----
    for (int c = 0; c < NCHUNK; c++) {
        CP_WAIT(1);          // W(c) complete (<=1 group pending)
        __syncthreads();     // stage c ready for all (incl. prior STS)

        if (c + 1 < NCHUNK) sts_x(c + 1);       // xc holds chunk c+1
        if (c + 2 < NCHUNK) ldg_half(c + 2, 0); // fp32 half A in flight

        const uint32_t sb = sbase + (uint32_t)(c & 1) * STAGE_BYTES;
        const uint32_t Xb = sb;
        const uint32_t Wb = sb + XS_BYTES;

#pragma unroll
        for (int ks = 0; ks < 4; ks++) {
            uint32_t a[4][4], b[4][4];
#pragma unroll
            for (int mt = 0; mt < 4; mt++)
                LDSM4(a[mt][0], a[mt][1], a[mt][2], a[mt][3],
                      Xb + xlb + (uint32_t)mt * 4096 + a_sw[ks]);
#pragma unroll
            for (int g = 0; g < 4; g++)
                LDSM4(b[g][0], b[g][1], b[g][2], b[g][3],
                      Wb + wlb + (uint32_t)g * 4096 + b_sw[ks]);
#pragma unroll
            for (int mt = 0; mt < 4; mt++)
#pragma unroll
                for (int nt = 0; nt < 8; nt++) {
                    const int g = nt >> 1, o = (nt & 1) * 2;
                    MMA16816(acc[mt][nt], a[mt], b[g][o], b[g][o + 1]);
                }
        }

        if (c + 2 < NCHUNK) { cvt_half(0); ldg_half(c + 2, 1); }

#pragma unroll
        for (int ks = 4; ks < 8; ks++) {
            uint32_t a[4][4], b[4][4];
#pragma unroll
            for (int mt = 0; mt < 4; mt++)
                LDSM4(a[mt][0], a[mt][1], a[mt][2], a[mt][3],
                      Xb + xlb + (uint32_t)mt * 4096 + a_sw[ks]);
#pragma unroll
            for (int g = 0; g < 4; g++)
                LDSM4(b[g][0], b[g][1], b[g][2], b[g][3],
                      Wb + wlb + (uint32_t)g * 4096 + b_sw[ks]);
#pragma unroll
            for (int mt = 0; mt < 4; mt++)
#pragma unroll
                for (int nt = 0; nt < 8; nt++) {
                    const int g = nt >> 1, o = (nt & 1) * 2;
                    MMA16816(acc[mt][nt], a[mt], b[g][o], b[g][o + 1]);
                }
        }

        if (c + 2 < NCHUNK) cvt_half(1);        // xc = chunk c+2 complete

        __syncthreads();     // all warps done reading stage c before refill
        if (c + 2 < NCHUNK) issue_w(c + 2);
        CP_COMMIT();         // unconditional: keeps group accounting exact
    }

    // ---- epilogue: apply absmax + bias, write out ----
#pragma unroll
    for (int nt = 0; nt < 8; nt++) {
        const int col = bn + wn + nt * 8 + 2 * (lane & 3);
        const float2 am = *reinterpret_cast<const float2*>(absmax + col);
        const float2 bi = *reinterpret_cast<const float2*>(bias + col);
#pragma unroll
        for (int mt = 0; mt < 4; mt++) {
            const int m0 = bm + wm + mt * 16 + (lane >> 2);
            float2 o0, o1;
            o0.x = acc[mt][nt][0] * am.x + bi.x;
            o0.y = acc[mt][nt][1] * am.y + bi.y;
            o1.x = acc[mt][nt][2] * am.x + bi.x;
            o1.y = acc[mt][nt][3] * am.y + bi.y;
            *reinterpret_cast<float2*>(out + (size_t)m0 * N_DIM + col) = o0;
            *reinterpret_cast<float2*>(out + (size_t)(m0 + 8) * N_DIM + col) = o1;
        }
    }
}

// ---------------- launch ----------------
extern "C" void kernel_launch(void* const* d_in, const int* in_sizes, int n_in,
                              void* d_out, int out_size) {
    const float* x      = (const float*)d_in[0];
    const int*   packed = (const int*)d_in[1];
    const float* absmax = (const float*)d_in[2];
    const float* bias   = (const float*)d_in[3];
    float*       out    = (float*)d_out;

    build_w_kernel<<<((size_t)N_DIM * KC64 * 8) / 256, 256>>>(packed);

    cudaFuncSetAttribute(nf4_hmma_kernel,
                         cudaFuncAttributeMaxDynamicSharedMemorySize, SMEM_DYN);
    dim3 grid(N_DIM / BN, M_DIM / BM);   // (16, 64)
    nf4_hmma_kernel<<<grid, NTH, SMEM_DYN>>>(x, absmax, bias, out);
}

// round 16
// speedup vs baseline: 1.1102x; 1.1102x over previous
#include <cuda_runtime.h>
#include <cuda_fp16.h>
#include <cstdint>

// NF4 quantized linear via single-term fp16 mma.sync (sm_103, non-'a' target).
// out[m][n] = sum_k x[m][k] * LUT[nib(packed[n][k])] * absmax[n] + bias[n]
// M=8192, N=4096, K=4096.
//
// fp16(x) * fp16(LUT) with fp32 accumulation: rel err ~2.6e-4 (< 1e-3 tol).
// R15 = R13 GEMM (best: BK=128, 2x96KB stages, 512 threads — measured at the
// legacy-HMMA issue-rate ceiling ~430 TF/s) + both image pre-passes merged
// into ONE kernel launch (block-range split; each phase already ~80% DRAM).
// R14's fused-X variant spilled (255 regs) and regressed — reverted.

#define M_DIM 8192
#define N_DIM 4096
#define K_DIM 4096
#define KC64  (K_DIM / 64)        // 64 k64-blocks per image row
#define KH    (K_DIM / 2)         // packed byte count per W row

#define BM 128
#define BN 256
#define NCHUNK 32                 // K-chunks of 128
#define NTH 512
#define STAGES 2
#define XS_BYTES 32768            // 128 rows x 256B
#define WS_BYTES 65536            // 256 rows x 256B
#define STAGE_BYTES (XS_BYTES + WS_BYTES)       // 98304
#define SMEM_DYN (STAGES * STAGE_BYTES)         // 196608

#define W_BLOCKS ((N_DIM * KC64 * 8) / 256)     // 8192
#define X_BLOCKS ((M_DIM * KC64 * 8) / 256)     // 16384

__device__ uint8_t g_xh[(size_t)M_DIM * KC64 * 128];   // 64 MB fp16 X image
__device__ uint8_t g_wh[(size_t)N_DIM * KC64 * 128];   // 32 MB fp16 W image

__constant__ float NF4_TAB[16] = {
    -1.0f, -0.6961928009986877f, -0.5250730514526367f, -0.39491748809814453f,
    -0.28444138169288635f, -0.18477343022823334f, -0.09105003625154495f, 0.0f,
    0.07958029955625534f, 0.16093020141124725f, 0.24611230194568634f,
    0.33791524171829224f, 0.44070982933044434f, 0.5626170039176941f,
    0.7229568362236023f, 1.0f};

// ---------------- PTX helpers (arch-agnostic, sm_80+) ----------------
#define CP_ASYNC16(smem_u32, gptr)                                             \
    asm volatile("cp.async.cg.shared.global [%0], [%1], 16;"                   \
                 :: "r"(smem_u32), "l"(gptr))
#define CP_COMMIT() asm volatile("cp.async.commit_group;" ::: "memory")
#define CP_WAIT(n)  asm volatile("cp.async.wait_group %0;" :: "n"(n) : "memory")

#define LDSM4(r0, r1, r2, r3, addr)                                            \
    asm volatile("ldmatrix.sync.aligned.m8n8.x4.shared.b16 {%0,%1,%2,%3}, [%4];" \
                 : "=r"(r0), "=r"(r1), "=r"(r2), "=r"(r3) : "r"(addr))

#define MMA16816(d, a, b0, b1)                                                 \
    asm volatile("mma.sync.aligned.m16n8k16.row.col.f32.f16.f16.f32 "          \
                 "{%0,%1,%2,%3}, {%4,%5,%6,%7}, {%8,%9}, {%0,%1,%2,%3};"       \
                 : "+f"((d)[0]), "+f"((d)[1]), "+f"((d)[2]), "+f"((d)[3])      \
                 : "r"((a)[0]), "r"((a)[1]), "r"((a)[2]), "r"((a)[3]),         \
                   "r"(b0), "r"(b1))

// pack (fp16(a), fp16(b)) -> u32 {b<<16 | a}
__device__ __forceinline__ uint32_t pack_f16x2(float a, float b) {
    uint32_t r;
    asm("cvt.rn.f16x2.f32 %0, %1, %2;" : "=r"(r) : "f"(b), "f"(a));
    return r;
}

// ---------------- merged pre-pass: W dequant image + X fp16 image ----------
// blocks [0, W_BLOCKS): NF4 dequant -> fp16 W image (coalesced, swizzled)
// blocks [W_BLOCKS, W_BLOCKS+X_BLOCKS): X fp32 -> fp16 image
__global__ __launch_bounds__(256)
void build_images_kernel(const float* __restrict__ x,
                         const int* __restrict__ packed) {
    if (blockIdx.x < W_BLOCKS) {
        __shared__ uint16_t lut[16];   // fp16 bits of NF4 level
        if (threadIdx.x < 16)
            lut[threadIdx.x] =
                (uint16_t)(pack_f16x2(NF4_TAB[threadIdx.x], 0.0f) & 0xFFFFu);
        __syncthreads();

        const size_t gt = (size_t)blockIdx.x * 256 + threadIdx.x;
        const size_t id = gt >> 3;                 // block index: n*KC64 + kc
        const int    j  = (int)(gt & 7);
        const int kc = (int)(id & (KC64 - 1));
        const int n  = (int)(id >> 6);

        const int4 pv = reinterpret_cast<const int4*>(packed)
                            [(size_t)n * (KH / 4) + kc * 8 + j];
        const uint32_t byts[4] = {(uint32_t)pv.x & 255u, (uint32_t)pv.y & 255u,
                                  (uint32_t)pv.z & 255u, (uint32_t)pv.w & 255u};
        uint32_t w[4];
#pragma unroll
        for (int e = 0; e < 4; e++) {
            const uint32_t b = byts[e];
            // k even = high nibble, k odd = low nibble
            w[e] = (uint32_t)lut[b >> 4] | ((uint32_t)lut[b & 15u] << 16);
        }
        *reinterpret_cast<uint4*>(g_wh + id * 128 + ((j ^ (n & 7)) * 16)) =
            make_uint4(w[0], w[1], w[2], w[3]);
    } else {
        const size_t gt = (size_t)(blockIdx.x - W_BLOCKS) * 256 + threadIdx.x;
        const size_t id = gt >> 3;                 // block index: m*KC64 + kc
        const int    j  = (int)(gt & 7);           // 16B sub-chunk
        const int kc = (int)(id & (KC64 - 1));
        const int m  = (int)(id >> 6);

        const float4* src = reinterpret_cast<const float4*>(
            x + (size_t)m * K_DIM + kc * 64 + j * 8);
        const float4 v0 = src[0];
        const float4 v1 = src[1];
        const uint4 o = make_uint4(pack_f16x2(v0.x, v0.y), pack_f16x2(v0.z, v0.w),
                                   pack_f16x2(v1.x, v1.y), pack_f16x2(v1.z, v1.w));
        *reinterpret_cast<uint4*>(g_xh + id * 128 + ((j ^ (m & 7)) * 16)) = o;
    }
}

// ---------------- main GEMM: BK=128, 2-stage cp.async, ldmatrix, HMMA ------
// (identical to R13 — best measured configuration)
__global__ __launch_bounds__(NTH, 1)
void nf4_hmma_kernel(const float* __restrict__ absmax,
                     const float* __restrict__ bias,
                     float* __restrict__ out) {
    extern __shared__ __align__(1024) uint8_t smem[];
    const uint32_t sbase = (uint32_t)__cvta_generic_to_shared(smem);

    const int tid  = threadIdx.x;
    const int wid  = tid >> 5;
    const int lane = tid & 31;
    const int bm = blockIdx.y * BM;
    const int bn = blockIdx.x * BN;
    const int wm = (wid & 1) * 64;     // 2 warps in m, warptile m=64
    const int wn = (wid >> 1) * 32;    // 8 warps in n, warptile n=32

    // ---- per-lane ldmatrix address components (verified R8-R13) ----
    const int s7 = lane & 7;
    const int rl = s7 + 8 * ((lane >> 3) & 1);       // A row-in-16
    const int pa = lane >> 4;                        // A k-half bit
    const int nl = s7 + 8 * (lane >> 4);             // B n-in-16
    const int kb = (lane >> 3) & 1;                  // B k-half bit
    // smem rows are 256B: [half0 128B | half1 128B], each half XOR-swizzled
    const uint32_t xlb = (uint32_t)(wm + rl) * 256;
    const uint32_t wlb = (uint32_t)(wn + nl) * 256;

    uint32_t a_sw[8], b_sw[8];   // per k16-step offsets within the 256B row
#pragma unroll
    for (int ks = 0; ks < 8; ks++) {
        const int half = ks >> 2, k4 = ks & 3;
        a_sw[ks] = (uint32_t)(half * 128 + ((2 * k4 + pa) ^ s7) * 16);
        b_sw[ks] = (uint32_t)(half * 128 + ((2 * k4 + kb) ^ s7) * 16);
    }

    // ---- cp.async producer: identity copy of two k64 image blocks per row --
    // X: 128 rows x 16 sub-chunks = 2048 -> 4/thread
    // W: 256 rows x 16 sub-chunks = 4096 -> 8/thread
    auto issue_stage = [&](int c) {
        const uint32_t sb = sbase + (uint32_t)(c & (STAGES - 1)) * STAGE_BYTES;
#pragma unroll
        for (int i = 0; i < 4; i++) {
            const int q = tid + i * NTH;
            const int row = q >> 4, sub = q & 15;
            const int half = sub >> 3, j = sub & 7;
            const uint8_t* gx =
                g_xh + (((size_t)(bm + row)) * KC64 + 2 * c + half) * 128 + j * 16;
            CP_ASYNC16(sb + row * 256 + half * 128 + j * 16, gx);
        }
#pragma unroll
        for (int i = 0; i < 8; i++) {
            const int q = tid + i * NTH;
            const int row = q >> 4, sub = q & 15;
            const int half = sub >> 3, j = sub & 7;
            const uint8_t* gw =
                g_wh + (((size_t)(bn + row)) * KC64 + 2 * c + half) * 128 + j * 16;
            CP_ASYNC16(sb + XS_BYTES + row * 256 + half * 128 + j * 16, gw);
        }
    };

    float acc[4][4][4];
#pragma unroll
    for (int mt = 0; mt < 4; mt++)
#pragma unroll
        for (int nt = 0; nt < 4; nt++)
#pragma unroll
            for (int e = 0; e < 4; e++) acc[mt][nt][e] = 0.0f;

    // ---- prologue: both stages in flight ----
    issue_stage(0); CP_COMMIT();
    issue_stage(1); CP_COMMIT();

    // ---- mainloop ----
    for (int c = 0; c < NCHUNK; c++) {
        CP_WAIT(1);          // group for chunk c complete (1 group may pend)
        __syncthreads();     // all threads' waits done -> stage visible to all

        const uint32_t sb = sbase + (uint32_t)(c & (STAGES - 1)) * STAGE_BYTES;
        const uint32_t Xb = sb;
        const uint32_t Wb = sb + XS_BYTES;

#pragma unroll
        for (int ks = 0; ks < 8; ks++) {
            uint32_t a[4][4];
#pragma unroll
            for (int mt = 0; mt < 4; mt++)
                LDSM4(a[mt][0], a[mt][1], a[mt][2], a[mt][3],
                      Xb + xlb + (uint32_t)mt * 4096 + a_sw[ks]);
            uint32_t b[2][4];
#pragma unroll
            for (int g = 0; g < 2; g++)
                LDSM4(b[g][0], b[g][1], b[g][2], b[g][3],
                      Wb + wlb + (uint32_t)g * 4096 + b_sw[ks]);
#pragma unroll
            for (int mt = 0; mt < 4; mt++)
#pragma unroll
                for (int nt = 0; nt < 4; nt++) {
                    const int g = nt >> 1, o = (nt & 1) * 2;
                    MMA16816(acc[mt][nt], a[mt], b[g][o], b[g][o + 1]);
                }
        }

        __syncthreads();     // all warps done reading stage c&1 before refill
        if (c + 2 < NCHUNK) issue_stage(c + 2);
        CP_COMMIT();         // keep group count in lockstep
    }

    // ---- epilogue: apply absmax + bias, write out ----
#pragma unroll
    for (int nt = 0; nt < 4; nt++) {
        const int col = bn + wn + nt * 8 + 2 * (lane & 3);
        const float2 am = *reinterpret_cast<const float2*>(absmax + col);
        const float2 bi = *reinterpret_cast<const float2*>(bias + col);
#pragma unroll
        for (int mt = 0; mt < 4; mt++) {
            const int m0 = bm + wm + mt * 16 + (lane >> 2);
            float2 o0, o1;
            o0.x = acc[mt][nt][0] * am.x + bi.x;
            o0.y = acc[mt][nt][1] * am.y + bi.y;
            o1.x = acc[mt][nt][2] * am.x + bi.x;
            o1.y = acc[mt][nt][3] * am.y + bi.y;
            *reinterpret_cast<float2*>(out + (size_t)m0 * N_DIM + col) = o0;
            *reinterpret_cast<float2*>(out + (size_t)(m0 + 8) * N_DIM + col) = o1;
        }
    }
}

// ---------------- launch ----------------
extern "C" void kernel_launch(void* const* d_in, const int* in_sizes, int n_in,
                              void* d_out, int out_size) {
    const float* x      = (const float*)d_in[0];
    const int*   packed = (const int*)d_in[1];
    const float* absmax = (const float*)d_in[2];
    const float* bias   = (const float*)d_in[3];
    float*       out    = (float*)d_out;

    build_images_kernel<<<W_BLOCKS + X_BLOCKS, 256>>>(x, packed);

    cudaFuncSetAttribute(nf4_hmma_kernel,
                         cudaFuncAttributeMaxDynamicSharedMemorySize, SMEM_DYN);
    dim3 grid(N_DIM / BN, M_DIM / BM);   // (16, 64)
    nf4_hmma_kernel<<<grid, NTH, SMEM_DYN>>>(absmax, bias, out);
}